// round 16
// baseline (speedup 1.0000x reference)
#include <cuda_runtime.h>

// LoRALayerNorm: x [B=2, S=4096, N=8192] fp32.
// PDL two-kernel structure (k1 -> g_scale/g_shift; k2 layernorm).
// k2 config: TPB=1024, VPT=2 — the one untried corner: register-resident
// single-read (only 8 data floats/thread -> ~32 regs) AND 100% theoretical
// occupancy (2 CTAs x 1024 thr = 64 warps/SM). Grid-dep sync placed right
// after load issue so the k1 wait is covered by in-flight DRAM loads.

#define N_FEAT 8192
#define N_ROWS 8192
#define RANK 4
#define SCALING_F 2.0f   // ALPHA/RANK = 8/4
#define EPS_F 1e-5f

#define TPB 1024
#define VPT 2            // float4 per thread: 1024*2*4 = 8192 floats per row
#define NWARP (TPB / 32) // 32 warps

#define K1_TPB 128
#define K1_CTAS (N_FEAT / K1_TPB)   // 64 CTAs, one feature per thread

__device__ float g_scale[N_FEAT];
__device__ float g_shift[N_FEAT];

// ---------------------------------------------------------------------------
// Kernel 1: low-rank diagonal -> scale/shift vectors (wide & shallow)
// ---------------------------------------------------------------------------
__global__ __launch_bounds__(K1_TPB)
void compute_vectors_kernel(const float* __restrict__ sA,
                            const float* __restrict__ sB,
                            const float* __restrict__ hA,
                            const float* __restrict__ hB) {
    cudaTriggerProgrammaticLaunchCompletion();

    const int i = blockIdx.x * K1_TPB + threadIdx.x;
    float4 a_s = __ldg(reinterpret_cast<const float4*>(sA + i * RANK));
    float4 a_h = __ldg(reinterpret_cast<const float4*>(hA + i * RANK));
    float sc = a_s.x * __ldg(&sB[0 * N_FEAT + i])
             + a_s.y * __ldg(&sB[1 * N_FEAT + i])
             + a_s.z * __ldg(&sB[2 * N_FEAT + i])
             + a_s.w * __ldg(&sB[3 * N_FEAT + i]);
    float sh = a_h.x * __ldg(&hB[0 * N_FEAT + i])
             + a_h.y * __ldg(&hB[1 * N_FEAT + i])
             + a_h.z * __ldg(&hB[2 * N_FEAT + i])
             + a_h.w * __ldg(&hB[3 * N_FEAT + i]);
    g_scale[i] = sc * SCALING_F;
    g_shift[i] = sh * SCALING_F;
}

// ---------------------------------------------------------------------------
// Kernel 2: one CTA (1024 thr) per row, register-resident single pass.
// ---------------------------------------------------------------------------
__global__ __launch_bounds__(TPB, 2)
void lora_layernorm_kernel(const float* __restrict__ x,
                           float* __restrict__ out) {
    const int row = blockIdx.x;
    const int tid = threadIdx.x;
    const float4* xrow = reinterpret_cast<const float4*>(x + (size_t)row * N_FEAT);
    float4* orow = reinterpret_cast<float4*>(out + (size_t)row * N_FEAT);

    // Streaming loads of x — issued first, independent of kernel 1.
    float4 v[VPT];
#pragma unroll
    for (int k = 0; k < VPT; k++) {
        v[k] = __ldcs(&xrow[tid + k * TPB]);
    }

    // Wait for kernel 1 while our loads are in flight; no-op for waves >= 2.
    cudaGridDependencySynchronize();

    float sum = 0.0f, sumsq = 0.0f;
#pragma unroll
    for (int k = 0; k < VPT; k++) {
        float4 t = v[k];
        sum += t.x + t.y + t.z + t.w;
        sumsq += t.x * t.x + t.y * t.y + t.z * t.z + t.w * t.w;
    }

#pragma unroll
    for (int off = 16; off > 0; off >>= 1) {
        sum += __shfl_xor_sync(0xffffffffu, sum, off);
        sumsq += __shfl_xor_sync(0xffffffffu, sumsq, off);
    }

    __shared__ float s_sum[NWARP];
    __shared__ float s_sumsq[NWARP];
    __shared__ float s_mean, s_rstd;
    const int wid = tid >> 5;
    const int lane = tid & 31;
    if (lane == 0) {
        s_sum[wid] = sum;
        s_sumsq[wid] = sumsq;
    }
    __syncthreads();
    if (wid == 0) {
        float a = s_sum[lane];    // NWARP == 32: every lane holds one warp
        float b = s_sumsq[lane];
#pragma unroll
        for (int off = 16; off > 0; off >>= 1) {
            a += __shfl_xor_sync(0xffffffffu, a, off);
            b += __shfl_xor_sync(0xffffffffu, b, off);
        }
        if (lane == 0) {
            float mean = a * (1.0f / N_FEAT);
            float var = b * (1.0f / N_FEAT) - mean * mean;
            s_mean = mean;
            s_rstd = rsqrtf(var + EPS_F);
        }
    }
    __syncthreads();
    const float mean = s_mean;
    const float rstd = s_rstd;

    const float4* scv = reinterpret_cast<const float4*>(g_scale);
    const float4* shv = reinterpret_cast<const float4*>(g_shift);
#pragma unroll
    for (int k = 0; k < VPT; k++) {
        const int idx = tid + k * TPB;
        float4 sc = __ldg(&scv[idx]);
        float4 sh = __ldg(&shv[idx]);
        float4 t = v[k];
        float4 o;
        o.x = (t.x - mean) * rstd * sc.x + sh.x;
        o.y = (t.y - mean) * rstd * sc.y + sh.y;
        o.z = (t.z - mean) * rstd * sc.z + sh.z;
        o.w = (t.w - mean) * rstd * sc.w + sh.w;
        __stcs(&orow[idx], o);
    }
}

// ---------------------------------------------------------------------------
extern "C" void kernel_launch(void* const* d_in, const int* in_sizes, int n_in,
                              void* d_out, int out_size) {
    const float* x = (const float*)d_in[0];
    const float* sA = (const float*)d_in[1];
    const float* sB = (const float*)d_in[2];
    const float* hA = (const float*)d_in[3];
    const float* hB = (const float*)d_in[4];
    float* out = (float*)d_out;

    compute_vectors_kernel<<<K1_CTAS, K1_TPB>>>(sA, sB, hA, hB);

    cudaLaunchConfig_t cfg = {};
    cfg.gridDim = dim3(N_ROWS, 1, 1);
    cfg.blockDim = dim3(TPB, 1, 1);
    cfg.dynamicSmemBytes = 0;
    cfg.stream = 0;
    cudaLaunchAttribute attr[1];
    attr[0].id = cudaLaunchAttributeProgrammaticStreamSerialization;
    attr[0].val.programmaticStreamSerializationAllowed = 1;
    cfg.attrs = attr;
    cfg.numAttrs = 1;
    cudaLaunchKernelEx(&cfg, lora_layernorm_kernel, x, out);
}

// round 17
// speedup vs baseline: 1.0898x; 1.0898x over previous
#include <cuda_runtime.h>

// LoRALayerNorm: x [B=2, S=4096, N=8192] fp32.
// PDL two-kernel structure:
//   k1 (64 CTAs x 128 thr): rank-4 diag -> g_scale/g_shift (wide & shallow).
//   k2 (8192 CTAs x 512): register-resident single-pass layernorm.
// k2 improvements over the 77.2us body:
//   - grid-dep sync right after load ISSUE (wait covered by DRAM latency).
//   - ONE __syncthreads total: after the partials land in smem, EVERY warp
//     redundantly butterfly-reduces the 16 partials (lane&15 read, xor
//     off 8/4/2/1) and computes mean/rstd locally. No second barrier, no
//     s_mean broadcast, warps flow independently into the epilogue.

#define N_FEAT 8192
#define N_ROWS 8192
#define RANK 4
#define SCALING_F 2.0f   // ALPHA/RANK = 8/4
#define EPS_F 1e-5f

#define TPB 512
#define VPT 4            // float4 per thread: 512*4*4 = 8192 floats per row
#define NWARP (TPB / 32) // 16

#define K1_TPB 128
#define K1_CTAS (N_FEAT / K1_TPB)   // 64 CTAs, one feature per thread

__device__ float g_scale[N_FEAT];
__device__ float g_shift[N_FEAT];

// ---------------------------------------------------------------------------
// Kernel 1: low-rank diagonal -> scale/shift vectors
// ---------------------------------------------------------------------------
__global__ __launch_bounds__(K1_TPB)
void compute_vectors_kernel(const float* __restrict__ sA,
                            const float* __restrict__ sB,
                            const float* __restrict__ hA,
                            const float* __restrict__ hB) {
    cudaTriggerProgrammaticLaunchCompletion();

    const int i = blockIdx.x * K1_TPB + threadIdx.x;
    float4 a_s = __ldg(reinterpret_cast<const float4*>(sA + i * RANK));
    float4 a_h = __ldg(reinterpret_cast<const float4*>(hA + i * RANK));
    float sc = a_s.x * __ldg(&sB[0 * N_FEAT + i])
             + a_s.y * __ldg(&sB[1 * N_FEAT + i])
             + a_s.z * __ldg(&sB[2 * N_FEAT + i])
             + a_s.w * __ldg(&sB[3 * N_FEAT + i]);
    float sh = a_h.x * __ldg(&hB[0 * N_FEAT + i])
             + a_h.y * __ldg(&hB[1 * N_FEAT + i])
             + a_h.z * __ldg(&hB[2 * N_FEAT + i])
             + a_h.w * __ldg(&hB[3 * N_FEAT + i]);
    g_scale[i] = sc * SCALING_F;
    g_shift[i] = sh * SCALING_F;
}

// ---------------------------------------------------------------------------
// Kernel 2: one CTA per row, register-resident, single barrier.
// ---------------------------------------------------------------------------
__global__ __launch_bounds__(TPB, 3)
void lora_layernorm_kernel(const float* __restrict__ x,
                           float* __restrict__ out) {
    const int row = blockIdx.x;
    const int tid = threadIdx.x;
    const int wid = tid >> 5;
    const int lane = tid & 31;
    const float4* xrow = reinterpret_cast<const float4*>(x + (size_t)row * N_FEAT);
    float4* orow = reinterpret_cast<float4*>(out + (size_t)row * N_FEAT);

    // Streaming loads of x — issued first, independent of kernel 1.
    float4 v[VPT];
#pragma unroll
    for (int k = 0; k < VPT; k++) {
        v[k] = __ldcs(&xrow[tid + k * TPB]);
    }

    // Wait for kernel 1 while our loads are in flight; no-op for waves >= 2.
    cudaGridDependencySynchronize();

    float sum = 0.0f, sumsq = 0.0f;
#pragma unroll
    for (int k = 0; k < VPT; k++) {
        float4 t = v[k];
        sum += t.x + t.y + t.z + t.w;
        sumsq += t.x * t.x + t.y * t.y + t.z * t.z + t.w * t.w;
    }

    // Warp-level reduce.
#pragma unroll
    for (int off = 16; off > 0; off >>= 1) {
        sum += __shfl_xor_sync(0xffffffffu, sum, off);
        sumsq += __shfl_xor_sync(0xffffffffu, sumsq, off);
    }

    __shared__ float s_sum[NWARP];
    __shared__ float s_sumsq[NWARP];
    if (lane == 0) {
        s_sum[wid] = sum;
        s_sumsq[wid] = sumsq;
    }
    __syncthreads();   // the ONLY barrier

    // Every warp redundantly reduces the 16 partials: lanes 0-15 and 16-31
    // each hold one copy of all 16 values; xor butterfly off 8/4/2/1 stays
    // within each 16-lane half and sums all 16 distinct partials into every
    // lane. No second barrier, no smem broadcast.
    float a = s_sum[lane & (NWARP - 1)];
    float b = s_sumsq[lane & (NWARP - 1)];
#pragma unroll
    for (int off = NWARP / 2; off > 0; off >>= 1) {
        a += __shfl_xor_sync(0xffffffffu, a, off);
        b += __shfl_xor_sync(0xffffffffu, b, off);
    }
    const float mean = a * (1.0f / N_FEAT);
    const float rstd = rsqrtf(b * (1.0f / N_FEAT) - mean * mean + EPS_F);

    const float4* scv = reinterpret_cast<const float4*>(g_scale);
    const float4* shv = reinterpret_cast<const float4*>(g_shift);
#pragma unroll
    for (int k = 0; k < VPT; k++) {
        const int idx = tid + k * TPB;
        float4 sc = __ldg(&scv[idx]);
        float4 sh = __ldg(&shv[idx]);
        float4 t = v[k];
        float4 o;
        o.x = (t.x - mean) * rstd * sc.x + sh.x;
        o.y = (t.y - mean) * rstd * sc.y + sh.y;
        o.z = (t.z - mean) * rstd * sc.z + sh.z;
        o.w = (t.w - mean) * rstd * sc.w + sh.w;
        __stcs(&orow[idx], o);
    }
}

// ---------------------------------------------------------------------------
extern "C" void kernel_launch(void* const* d_in, const int* in_sizes, int n_in,
                              void* d_out, int out_size) {
    const float* x = (const float*)d_in[0];
    const float* sA = (const float*)d_in[1];
    const float* sB = (const float*)d_in[2];
    const float* hA = (const float*)d_in[3];
    const float* hB = (const float*)d_in[4];
    float* out = (float*)d_out;

    compute_vectors_kernel<<<K1_CTAS, K1_TPB>>>(sA, sB, hA, hB);

    cudaLaunchConfig_t cfg = {};
    cfg.gridDim = dim3(N_ROWS, 1, 1);
    cfg.blockDim = dim3(TPB, 1, 1);
    cfg.dynamicSmemBytes = 0;
    cfg.stream = 0;
    cudaLaunchAttribute attr[1];
    attr[0].id = cudaLaunchAttributeProgrammaticStreamSerialization;
    attr[0].val.programmaticStreamSerializationAllowed = 1;
    cfg.attrs = attr;
    cfg.numAttrs = 1;
    cudaLaunchKernelEx(&cfg, lora_layernorm_kernel, x, out);
}